// round 1
// baseline (speedup 1.0000x reference)
#include <cuda_runtime.h>
#include <math.h>

#define D_MODEL 1024
#define NHEAD   16
#define HDIM    64
#define DFF_    4096
#define NLAYER  6
#define BATCH   4
#define SEQ     2048
#define NTOK    (BATCH*SEQ)      /* 8192 */
#define KSEL    1024
#define NSEL    (BATCH*KSEL)     /* 4096 */

// ---------------- scratch (device globals; no allocations allowed) ----------
__device__ __align__(256) float g_x   [NTOK*D_MODEL];
__device__ __align__(256) float g_xsel[NSEL*D_MODEL];
__device__ __align__(256) float g_qkv [NTOK*3*D_MODEL];
__device__ __align__(256) float g_attn[NTOK*D_MODEL];
__device__ __align__(256) float g_t1  [NTOK*D_MODEL];
__device__ __align__(256) float g_t2  [NTOK*D_MODEL];
__device__ __align__(256) float g_ff  [NTOK*DFF_];
__device__ __align__(256) float g_rs  [BATCH*SEQ];
__device__ __align__(256) int   g_sel [BATCH*KSEL];
__device__ __align__(256) float g_w   [BATCH*KSEL];

// ---------------- simple float4 copy ---------------------------------------
__global__ void copy_f4(const float4* __restrict__ src, float4* __restrict__ dst, int n4) {
    int i = blockIdx.x * blockDim.x + threadIdx.x;
    if (i < n4) dst[i] = src[i];
}

// ---------------- SGEMM: C[N,M] = A[N,K] @ W[M,K]^T + bias (opt relu) ------
// 128x128 tile, K-step 8, 256 threads, 8x8 micro-tile per thread.
template<int RELU>
__global__ __launch_bounds__(256, 2)
void sgemm128(const float* __restrict__ A, const float* __restrict__ W,
              const float* __restrict__ bias, float* __restrict__ C,
              int N, int M, int K) {
    __shared__ float As[8][128];
    __shared__ float Ws[8][128];
    const int t  = threadIdx.x;
    const int tx = t & 15;          // col group
    const int ty = t >> 4;          // row group
    const int cm = blockIdx.x * 128;
    const int rn = blockIdx.y * 128;
    const int lr = t >> 1;          // load row 0..127
    const int lk = (t & 1) * 4;     // load k offset 0 or 4

    const float* Aptr = A + (size_t)(rn + lr) * K + lk;
    const float* Wptr = W + (size_t)(cm + lr) * K + lk;

    float acc[8][8];
    #pragma unroll
    for (int i = 0; i < 8; i++)
        #pragma unroll
        for (int j = 0; j < 8; j++) acc[i][j] = 0.f;

    for (int kt = 0; kt < K; kt += 8) {
        float4 av = *(const float4*)(Aptr + kt);
        float4 wv = *(const float4*)(Wptr + kt);
        As[lk+0][lr] = av.x; As[lk+1][lr] = av.y; As[lk+2][lr] = av.z; As[lk+3][lr] = av.w;
        Ws[lk+0][lr] = wv.x; Ws[lk+1][lr] = wv.y; Ws[lk+2][lr] = wv.z; Ws[lk+3][lr] = wv.w;
        __syncthreads();
        #pragma unroll
        for (int k = 0; k < 8; k++) {
            float a[8], b[8];
            *(float4*)&a[0] = *(const float4*)&As[k][ty*8];
            *(float4*)&a[4] = *(const float4*)&As[k][ty*8 + 4];
            *(float4*)&b[0] = *(const float4*)&Ws[k][tx*8];
            *(float4*)&b[4] = *(const float4*)&Ws[k][tx*8 + 4];
            #pragma unroll
            for (int i = 0; i < 8; i++)
                #pragma unroll
                for (int j = 0; j < 8; j++)
                    acc[i][j] += a[i] * b[j];
        }
        __syncthreads();
    }

    #pragma unroll
    for (int i = 0; i < 8; i++) {
        int row = rn + ty*8 + i;
        float* Crow = C + (size_t)row * M + cm + tx*8;
        #pragma unroll
        for (int j = 0; j < 8; j++) {
            float v = acc[i][j] + bias[cm + tx*8 + j];
            if (RELU) v = fmaxf(v, 0.f);
            acc[i][j] = v;
        }
        *(float4*)(Crow)     = *(float4*)&acc[i][0];
        *(float4*)(Crow + 4) = *(float4*)&acc[i][4];
    }
}

// ---------------- flash attention (fp32, HD=64) -----------------------------
// Block = (qtile of 64, head, batch). 256 threads, 4x4 micro per thread.
#define PS_STRIDE 65
#define ATTN_SMEM ((3*64*64 + 64*PS_STRIDE + 3*64) * 4)

__global__ __launch_bounds__(256)
void attn_kernel(const float* __restrict__ qkv, float* __restrict__ out,
                 int T) {
    extern __shared__ float sm[];
    float* Qs   = sm;                 // [d][q]  64x64
    float* Ks   = Qs + 64*64;         // [d][k]  64x64
    float* Vs   = Ks + 64*64;         // [k][d]  64x64
    float* Ps   = Vs + 64*64;         // [q][k]  64x65 (padded)
    float* mrow = Ps + 64*PS_STRIDE;
    float* lrow = mrow + 64;
    float* arow = lrow + 64;

    const int t  = threadIdx.x;
    const int tx = t & 15;
    const int ty = t >> 4;
    const int qt = blockIdx.x, h = blockIdx.y, b = blockIdx.z;
    const int stride = 3 * D_MODEL;

    const float* qbase = qkv + (size_t)(b*T + qt*64) * stride + h*HDIM;
    for (int it = t; it < 64*16; it += 256) {
        int q = it >> 4; int dg = (it & 15) * 4;
        float4 v = *(const float4*)(qbase + (size_t)q*stride + dg);
        Qs[(dg+0)*64 + q] = v.x; Qs[(dg+1)*64 + q] = v.y;
        Qs[(dg+2)*64 + q] = v.z; Qs[(dg+3)*64 + q] = v.w;
    }
    if (t < 64) { mrow[t] = -1e30f; lrow[t] = 0.f; }

    float oacc[4][4];
    #pragma unroll
    for (int i = 0; i < 4; i++)
        #pragma unroll
        for (int j = 0; j < 4; j++) oacc[i][j] = 0.f;

    const float* kbase0 = qkv + (size_t)(b*T) * stride +     D_MODEL + h*HDIM;
    const float* vbase0 = qkv + (size_t)(b*T) * stride + 2 * D_MODEL + h*HDIM;
    const int nkt = T / 64;

    for (int kt2 = 0; kt2 < nkt; kt2++) {
        __syncthreads();   // protect Ks/Vs/Ps reuse from previous iteration
        const float* kb = kbase0 + (size_t)kt2 * 64 * stride;
        const float* vb = vbase0 + (size_t)kt2 * 64 * stride;
        for (int it = t; it < 64*16; it += 256) {
            int kk = it >> 4; int dg = (it & 15) * 4;
            float4 kv = *(const float4*)(kb + (size_t)kk*stride + dg);
            Ks[(dg+0)*64 + kk] = kv.x; Ks[(dg+1)*64 + kk] = kv.y;
            Ks[(dg+2)*64 + kk] = kv.z; Ks[(dg+3)*64 + kk] = kv.w;
            float4 vv = *(const float4*)(vb + (size_t)kk*stride + dg);
            *(float4*)&Vs[kk*64 + dg] = vv;
        }
        __syncthreads();

        // S tile: s[i][j] = q(ty*4+i) . k(tx*4+j)
        float s[4][4];
        #pragma unroll
        for (int i = 0; i < 4; i++)
            #pragma unroll
            for (int j = 0; j < 4; j++) s[i][j] = 0.f;
        #pragma unroll 16
        for (int d = 0; d < 64; d++) {
            float4 a  = *(const float4*)&Qs[d*64 + ty*4];
            float4 bb = *(const float4*)&Ks[d*64 + tx*4];
            s[0][0] += a.x*bb.x; s[0][1] += a.x*bb.y; s[0][2] += a.x*bb.z; s[0][3] += a.x*bb.w;
            s[1][0] += a.y*bb.x; s[1][1] += a.y*bb.y; s[1][2] += a.y*bb.z; s[1][3] += a.y*bb.w;
            s[2][0] += a.z*bb.x; s[2][1] += a.z*bb.y; s[2][2] += a.z*bb.z; s[2][3] += a.z*bb.w;
            s[3][0] += a.w*bb.x; s[3][1] += a.w*bb.y; s[3][2] += a.w*bb.z; s[3][3] += a.w*bb.w;
        }
        #pragma unroll
        for (int i = 0; i < 4; i++)
            #pragma unroll
            for (int j = 0; j < 4; j++)
                Ps[(ty*4 + i)*PS_STRIDE + tx*4 + j] = s[i][j] * 0.125f;
        __syncthreads();

        // online softmax update, one thread per row
        if (t < 64) {
            float mo = mrow[t];
            float mt = -1e30f;
            #pragma unroll 8
            for (int k2 = 0; k2 < 64; k2++) mt = fmaxf(mt, Ps[t*PS_STRIDE + k2]);
            float mn = fmaxf(mo, mt);
            float al = __expf(mo - mn);
            float sum = 0.f;
            #pragma unroll 8
            for (int k2 = 0; k2 < 64; k2++) {
                float p = __expf(Ps[t*PS_STRIDE + k2] - mn);
                Ps[t*PS_STRIDE + k2] = p;
                sum += p;
            }
            mrow[t] = mn;
            lrow[t] = lrow[t]*al + sum;
            arow[t] = al;
        }
        __syncthreads();

        // O accumulation: oacc[i][j] over d = tx*4+j
        float al0 = arow[ty*4+0], al1 = arow[ty*4+1], al2 = arow[ty*4+2], al3 = arow[ty*4+3];
        #pragma unroll
        for (int j = 0; j < 4; j++) {
            oacc[0][j] *= al0; oacc[1][j] *= al1; oacc[2][j] *= al2; oacc[3][j] *= al3;
        }
        #pragma unroll 8
        for (int k2 = 0; k2 < 64; k2++) {
            float4 v = *(const float4*)&Vs[k2*64 + tx*4];
            float p0 = Ps[(ty*4+0)*PS_STRIDE + k2];
            float p1 = Ps[(ty*4+1)*PS_STRIDE + k2];
            float p2 = Ps[(ty*4+2)*PS_STRIDE + k2];
            float p3 = Ps[(ty*4+3)*PS_STRIDE + k2];
            oacc[0][0] += p0*v.x; oacc[0][1] += p0*v.y; oacc[0][2] += p0*v.z; oacc[0][3] += p0*v.w;
            oacc[1][0] += p1*v.x; oacc[1][1] += p1*v.y; oacc[1][2] += p1*v.z; oacc[1][3] += p1*v.w;
            oacc[2][0] += p2*v.x; oacc[2][1] += p2*v.y; oacc[2][2] += p2*v.z; oacc[2][3] += p2*v.w;
            oacc[3][0] += p3*v.x; oacc[3][1] += p3*v.y; oacc[3][2] += p3*v.z; oacc[3][3] += p3*v.w;
        }
    }

    const int n0 = b*T + qt*64;
    #pragma unroll
    for (int i = 0; i < 4; i++) {
        int q = ty*4 + i;
        float inv = 1.f / lrow[q];
        float4 o = make_float4(oacc[i][0]*inv, oacc[i][1]*inv, oacc[i][2]*inv, oacc[i][3]*inv);
        *(float4*)(out + (size_t)(n0 + q)*D_MODEL + h*HDIM + tx*4) = o;
    }
}

// ---------------- residual add + LayerNorm ----------------------------------
__global__ __launch_bounds__(256)
void addln_kernel(const float* __restrict__ a, const float* __restrict__ r,
                  const float* __restrict__ g, const float* __restrict__ be,
                  float* __restrict__ out) {
    __shared__ float rsum[256], rsq[256];
    const int n = blockIdx.x, t = threadIdx.x;
    float4 av = *(const float4*)(a + (size_t)n*D_MODEL + t*4);
    float4 rv = *(const float4*)(r + (size_t)n*D_MODEL + t*4);
    float x0 = av.x + rv.x, x1 = av.y + rv.y, x2 = av.z + rv.z, x3 = av.w + rv.w;
    rsum[t] = x0 + x1 + x2 + x3;
    rsq [t] = x0*x0 + x1*x1 + x2*x2 + x3*x3;
    __syncthreads();
    for (int off = 128; off > 0; off >>= 1) {
        if (t < off) { rsum[t] += rsum[t+off]; rsq[t] += rsq[t+off]; }
        __syncthreads();
    }
    float mu  = rsum[0] * (1.f/1024.f);
    float var = rsq[0]  * (1.f/1024.f) - mu*mu;
    float rstd = rsqrtf(var + 1e-5f);
    float4 gv = *(const float4*)(g  + t*4);
    float4 bv = *(const float4*)(be + t*4);
    float4 o;
    o.x = (x0 - mu)*rstd*gv.x + bv.x;
    o.y = (x1 - mu)*rstd*gv.y + bv.y;
    o.z = (x2 - mu)*rstd*gv.z + bv.z;
    o.w = (x3 - mu)*rstd*gv.w + bv.w;
    *(float4*)(out + (size_t)n*D_MODEL + t*4) = o;
}

// ---------------- router score ----------------------------------------------
__global__ __launch_bounds__(256)
void router_kernel(const float* __restrict__ x, const float* __restrict__ rw,
                   float* __restrict__ out) {
    __shared__ float red[256];
    const int n = blockIdx.x, t = threadIdx.x;
    float4 xv = *(const float4*)(x + (size_t)n*D_MODEL + t*4);
    float4 wv = *(const float4*)(rw + t*4);
    red[t] = xv.x*wv.x + xv.y*wv.y + xv.z*wv.z + xv.w*wv.w;
    __syncthreads();
    for (int off = 128; off > 0; off >>= 1) {
        if (t < off) red[t] += red[t+off];
        __syncthreads();
    }
    if (t == 0) out[n] = red[0];
}

// ---------------- top-k via bitonic sort (desc value, asc index) ------------
__global__ __launch_bounds__(1024)
void topk_kernel(const float* __restrict__ scores, int* __restrict__ sel,
                 float* __restrict__ wout) {
    __shared__ float v[2048];
    __shared__ int  id[2048];
    const int b = blockIdx.x, t = threadIdx.x;
    v[t]        = scores[b*SEQ + t];        id[t]        = t;
    v[t + 1024] = scores[b*SEQ + t + 1024]; id[t + 1024] = t + 1024;
    __syncthreads();
    for (int k = 2; k <= 2048; k <<= 1) {
        for (int j = k >> 1; j > 0; j >>= 1) {
            #pragma unroll
            for (int s = 0; s < 2; s++) {
                int i = t + s*1024;
                int ixj = i ^ j;
                if (ixj > i) {
                    float vi = v[i], vj = v[ixj];
                    int   ii = id[i], ij = id[ixj];
                    bool before = (vi > vj) || (vi == vj && ii < ij);
                    bool up = ((i & k) == 0);
                    bool dosw = up ? (!before) : before;
                    if (dosw) { v[i] = vj; v[ixj] = vi; id[i] = ij; id[ixj] = ii; }
                }
            }
            __syncthreads();
        }
    }
    // first KSEL entries are the top-k
    sel [b*KSEL + t] = id[t];
    wout[b*KSEL + t] = 1.f / (1.f + expf(-v[t]));
}

// ---------------- gather / scatter ------------------------------------------
__global__ __launch_bounds__(256)
void gather_kernel(const float* __restrict__ x, const int* __restrict__ sel,
                   float* __restrict__ xs) {
    const int row = blockIdx.x;
    const int b = row >> 10;
    const int src = b*SEQ + sel[row];
    const int t = threadIdx.x;
    float4 v = *(const float4*)(x + (size_t)src*D_MODEL + t*4);
    *(float4*)(xs + (size_t)row*D_MODEL + t*4) = v;
}

__global__ __launch_bounds__(256)
void scatter_kernel(float* __restrict__ x, const int* __restrict__ sel,
                    const float* __restrict__ w, const float* __restrict__ xs,
                    const float* __restrict__ proc) {
    const int row = blockIdx.x;
    const int b = row >> 10;
    const int dst = b*SEQ + sel[row];
    const float wv = w[row];
    const int t = threadIdx.x;
    float4 p  = *(const float4*)(proc + (size_t)row*D_MODEL + t*4);
    float4 s  = *(const float4*)(xs   + (size_t)row*D_MODEL + t*4);
    float4 xv = *(float4*)(x + (size_t)dst*D_MODEL + t*4);
    xv.x += (p.x - s.x)*wv;
    xv.y += (p.y - s.y)*wv;
    xv.z += (p.z - s.z)*wv;
    xv.w += (p.w - s.w)*wv;
    *(float4*)(x + (size_t)dst*D_MODEL + t*4) = xv;
}

// ---------------- host-side encoder layer ------------------------------------
static void run_encoder(const float* Xin, float* Xout, int Ncur, int Tcur, int Bcur,
                        const float* Wq, const float* bq, const float* Wo, const float* bo,
                        const float* W1, const float* b1, const float* W2, const float* b2,
                        const float* g1, const float* be1, const float* g2, const float* be2,
                        float* qkv, float* attnb, float* t1, float* t2, float* ff) {
    sgemm128<0><<<dim3(3*D_MODEL/128, Ncur/128), 256>>>(Xin, Wq, bq, qkv, Ncur, 3*D_MODEL, D_MODEL);
    attn_kernel<<<dim3(Tcur/64, NHEAD, Bcur), 256, ATTN_SMEM>>>(qkv, attnb, Tcur);
    sgemm128<0><<<dim3(D_MODEL/128, Ncur/128), 256>>>(attnb, Wo, bo, t2, Ncur, D_MODEL, D_MODEL);
    addln_kernel<<<Ncur, 256>>>(Xin, t2, g1, be1, t1);
    sgemm128<1><<<dim3(DFF_/128, Ncur/128), 256>>>(t1, W1, b1, ff, Ncur, DFF_, D_MODEL);
    sgemm128<0><<<dim3(D_MODEL/128, Ncur/128), 256>>>(ff, W2, b2, t2, Ncur, D_MODEL, DFF_);
    addln_kernel<<<Ncur, 256>>>(t1, t2, g2, be2, Xout);
}

extern "C" void kernel_launch(void* const* d_in, const int* in_sizes, int n_in,
                              void* d_out, int out_size) {
    (void)in_sizes; (void)n_in; (void)out_size;
    const float* x    = (const float*)d_in[0];
    const float* Wqkv = (const float*)d_in[1];
    const float* bqkv = (const float*)d_in[2];
    const float* Wo   = (const float*)d_in[3];
    const float* bo   = (const float*)d_in[4];
    const float* W1   = (const float*)d_in[5];
    const float* b1   = (const float*)d_in[6];
    const float* W2   = (const float*)d_in[7];
    const float* b2   = (const float*)d_in[8];
    const float* g1   = (const float*)d_in[9];
    const float* be1  = (const float*)d_in[10];
    const float* g2   = (const float*)d_in[11];
    const float* be2  = (const float*)d_in[12];
    const float* rw   = (const float*)d_in[13];

    float *gx, *gxsel, *gqkv, *gattn, *gt1, *gt2, *gff, *grs, *gw; int* gsel;
    cudaGetSymbolAddress((void**)&gx,    g_x);
    cudaGetSymbolAddress((void**)&gxsel, g_xsel);
    cudaGetSymbolAddress((void**)&gqkv,  g_qkv);
    cudaGetSymbolAddress((void**)&gattn, g_attn);
    cudaGetSymbolAddress((void**)&gt1,   g_t1);
    cudaGetSymbolAddress((void**)&gt2,   g_t2);
    cudaGetSymbolAddress((void**)&gff,   g_ff);
    cudaGetSymbolAddress((void**)&grs,   g_rs);
    cudaGetSymbolAddress((void**)&gsel,  g_sel);
    cudaGetSymbolAddress((void**)&gw,    g_w);

    cudaFuncSetAttribute(attn_kernel, cudaFuncAttributeMaxDynamicSharedMemorySize, ATTN_SMEM);

    const int n4 = NTOK*D_MODEL/4;
    copy_f4<<<(n4 + 255)/256, 256>>>((const float4*)x, (float4*)gx, n4);

    for (int L = 0; L < NLAYER; L++) {
        const float* Wq_l  = Wqkv + (size_t)L*3*D_MODEL*D_MODEL;
        const float* bq_l  = bqkv + (size_t)L*3*D_MODEL;
        const float* Wo_l  = Wo   + (size_t)L*D_MODEL*D_MODEL;
        const float* bo_l  = bo   + (size_t)L*D_MODEL;
        const float* W1_l  = W1   + (size_t)L*DFF_*D_MODEL;
        const float* b1_l  = b1   + (size_t)L*DFF_;
        const float* W2_l  = W2   + (size_t)L*D_MODEL*DFF_;
        const float* b2_l  = b2   + (size_t)L*D_MODEL;
        const float* g1_l  = g1   + (size_t)L*D_MODEL;
        const float* be1_l = be1  + (size_t)L*D_MODEL;
        const float* g2_l  = g2   + (size_t)L*D_MODEL;
        const float* be2_l = be2  + (size_t)L*D_MODEL;

        if (L & 1) {
            router_kernel<<<NTOK, 256>>>(gx, rw + (size_t)L*D_MODEL, grs);
            topk_kernel<<<BATCH, 1024>>>(grs, gsel, gw);
            gather_kernel<<<NSEL, 256>>>(gx, gsel, gxsel);
            run_encoder(gxsel, gattn, NSEL, KSEL, BATCH,
                        Wq_l, bq_l, Wo_l, bo_l, W1_l, b1_l, W2_l, b2_l,
                        g1_l, be1_l, g2_l, be2_l,
                        gqkv, gattn, gt1, gt2, gff);
            scatter_kernel<<<NSEL, 256>>>(gx, gsel, gw, gxsel, gattn);
        } else {
            run_encoder(gx, gx, NTOK, SEQ, BATCH,
                        Wq_l, bq_l, Wo_l, bo_l, W1_l, b1_l, W2_l, b2_l,
                        g1_l, be1_l, g2_l, be2_l,
                        gqkv, gattn, gt1, gt2, gff);
        }
    }

    copy_f4<<<(n4 + 255)/256, 256>>>((const float4*)gx, (float4*)d_out, n4);
}